// round 3
// baseline (speedup 1.0000x reference)
#include <cuda_runtime.h>
#include <cuda_bf16.h>
#include <math.h>
#include <stdint.h>

// Problem constants
#define NTOK 1024
#define DMODEL 512
#define HID 2048
#define NEXP 8
#define NPAIR 2048
#define KSPLIT 4          // FC2 split-K slices (each 512)

// ---------------- scratch (device globals; no allocation) ----------------
__device__ __nv_bfloat16 g_inph[NTOK * DMODEL];   // 1MB
__device__ __nv_bfloat16 g_inpl[NTOK * DMODEL];
__device__ __nv_bfloat16 g_hh[NPAIR * HID];       // 8MB
__device__ __nv_bfloat16 g_hl[NPAIR * HID];       // 8MB
__device__ float g_y2p[KSPLIT * NPAIR * DMODEL];  // 16.8MB partial FC2 outputs
__device__ int   g_cnt[NEXP];
__device__ int   g_off[NEXP];
__device__ int   g_tokexp[NPAIR];
__device__ float g_score[NPAIR];
__device__ int   g_pos[NPAIR];
__device__ int   g_pair_token[NPAIR];

// ---------------- helpers ----------------
__device__ __forceinline__ uint32_t b2u(__nv_bfloat162 v) {
    return *reinterpret_cast<uint32_t*>(&v);
}
// truncation split of 4 floats -> packed bf16 hi (2 words) + lo (2 words)
__device__ __forceinline__ void split4(float4 v, uint32_t& h01, uint32_t& h23,
                                       uint32_t& l01, uint32_t& l23) {
    uint32_t bx = __float_as_uint(v.x), by = __float_as_uint(v.y);
    uint32_t bz = __float_as_uint(v.z), bw = __float_as_uint(v.w);
    h01 = __byte_perm(bx, by, 0x7632);
    h23 = __byte_perm(bz, bw, 0x7632);
    float r0 = v.x - __uint_as_float(bx & 0xffff0000u);
    float r1 = v.y - __uint_as_float(by & 0xffff0000u);
    float r2 = v.z - __uint_as_float(bz & 0xffff0000u);
    float r3 = v.w - __uint_as_float(bw & 0xffff0000u);
    l01 = b2u(__floats2bfloat162_rn(r0, r1));
    l23 = b2u(__floats2bfloat162_rn(r2, r3));
}
__device__ __forceinline__ void split2(float x, float y, uint32_t& h, uint32_t& l) {
    uint32_t bx = __float_as_uint(x), by = __float_as_uint(y);
    h = __byte_perm(bx, by, 0x7632);
    float r0 = x - __uint_as_float(bx & 0xffff0000u);
    float r1 = y - __uint_as_float(by & 0xffff0000u);
    l = b2u(__floats2bfloat162_rn(r0, r1));
}
// erf-GELU via Abramowitz-Stegun 7.1.26 (|err_erf| < 1.5e-7)
__device__ __forceinline__ float gelu_erf(float x) {
    float z = fabsf(x) * 0.70710678118654752f;
    float t = __frcp_rn(fmaf(0.3275911f, z, 1.0f));
    float p = fmaf(fmaf(fmaf(fmaf(1.061405429f, t, -1.453152027f), t,
                             1.421413741f), t, -0.284496736f), t, 0.254829592f) * t;
    float er = 1.0f - p * __expf(-z * z);
    return x * 0.5f * (1.0f + copysignf(er, x));
}
__device__ __forceinline__ void ldsm_x4(uint32_t addr, uint32_t* r) {
    asm volatile("ldmatrix.sync.aligned.m8n8.x4.shared.b16 {%0,%1,%2,%3}, [%4];"
                 : "=r"(r[0]), "=r"(r[1]), "=r"(r[2]), "=r"(r[3]) : "r"(addr));
}
__device__ __forceinline__ void mma_bf16(float* d, const uint32_t* a,
                                         uint32_t b0, uint32_t b1) {
    asm volatile("mma.sync.aligned.m16n8k16.row.col.f32.bf16.bf16.f32 "
                 "{%0,%1,%2,%3},{%4,%5,%6,%7},{%8,%9},{%0,%1,%2,%3};"
                 : "+f"(d[0]), "+f"(d[1]), "+f"(d[2]), "+f"(d[3])
                 : "r"(a[0]), "r"(a[1]), "r"(a[2]), "r"(a[3]), "r"(b0), "r"(b1));
}

// ---------------- kernel: convert inp to bf16 hi/lo ----------------
__global__ void cvt_inp(const float* __restrict__ x) {
    int i = blockIdx.x * blockDim.x + threadIdx.x;   // over float4s
    if (i >= NTOK * DMODEL / 4) return;
    float4 v = reinterpret_cast<const float4*>(x)[i];
    uint32_t h01, h23, l01, l23;
    split4(v, h01, h23, l01, l23);
    reinterpret_cast<uint2*>(g_inph)[i] = make_uint2(h01, h23);
    reinterpret_cast<uint2*>(g_inpl)[i] = make_uint2(l01, l23);
}

// ---------------- kernel: gate (one warp per token, no atomics) ----------------
__global__ void gate_kernel(const float* __restrict__ inp,
                            const float* __restrict__ gw,
                            const float* __restrict__ gb) {
    int tok  = (blockIdx.x * blockDim.x + threadIdx.x) >> 5;
    int lane = threadIdx.x & 31;
    if (tok >= NTOK) return;
    const float* x = inp + (size_t)tok * DMODEL;
    float acc[NEXP];
#pragma unroll
    for (int e = 0; e < NEXP; e++) acc[e] = 0.f;
    for (int d = lane; d < DMODEL; d += 32) {
        float xv = x[d];
#pragma unroll
        for (int e = 0; e < NEXP; e++) acc[e] += xv * gw[e * DMODEL + d];
    }
#pragma unroll
    for (int e = 0; e < NEXP; e++)
#pragma unroll
        for (int o = 16; o; o >>= 1) acc[e] += __shfl_xor_sync(~0u, acc[e], o);
    if (lane == 0) {
        float best = -1e30f, best2 = -1e30f; int bi = 0, bi2 = 0;
#pragma unroll
        for (int e = 0; e < NEXP; e++) {
            float v = acc[e] + gb[e];
            if (v > best)       { best2 = best; bi2 = bi; best = v; bi = e; }
            else if (v > best2) { best2 = v; bi2 = e; }
        }
        float ed = expf(best2 - best);
        g_tokexp[tok * 2 + 0] = bi;
        g_tokexp[tok * 2 + 1] = bi2;
        g_score[tok * 2 + 0] = 1.f / (1.f + ed);
        g_score[tok * 2 + 1] = ed / (1.f + ed);
    }
}

// ---------------- kernel: scan + scatter (single block, shared atomics) ----------------
__global__ void scan_scatter() {
    __shared__ int hist[NEXP], cur[NEXP];
    int t = threadIdx.x;                   // 1024 threads, 2 pairs each
    if (t < NEXP) hist[t] = 0;
    __syncthreads();
    int e0 = g_tokexp[t], e1 = g_tokexp[t + 1024];
    atomicAdd(&hist[e0], 1);
    atomicAdd(&hist[e1], 1);
    __syncthreads();
    if (t == 0) {
        int s = 0;
        for (int e = 0; e < NEXP; e++) {
            g_off[e] = s; cur[e] = s; g_cnt[e] = hist[e]; s += hist[e];
        }
    }
    __syncthreads();
    int p0 = atomicAdd(&cur[e0], 1);
    g_pos[t] = p0; g_pair_token[p0] = t >> 1;
    int p1 = atomicAdd(&cur[e1], 1);
    g_pos[t + 1024] = p1; g_pair_token[p1] = (t + 1024) >> 1;
}

// ---------------- weight-stationary grouped GEMM ----------------
// CTA = (expert, 64-col slice [, k-slice]) ; converts its W slice once (full
// k-extent KT=512 in SMEM as bf16 hi/lo), then loops m-blocks of 128 rows.
// EPI 0: bias + GELU -> bf16 hi/lo (FC1).  EPI 1: fp32 partial (+bias if ks==0) (FC2).
#define BM 128
#define BN 64
#define KT 512
#define BKC 64
#define PKA 72            // A chunk pitch (elems); 144B stride, ldsm conflict-free
#define PKB 520           // B full-K pitch; 1040B stride, ldsm conflict-free

template<int EPI, bool GATHER, bool SPLITK>
__global__ __launch_bounds__(256)
void moe_fc(const __nv_bfloat16* __restrict__ Agh,  // A hi (pre-converted)
            const __nv_bfloat16* __restrict__ Agl,  // A lo
            int astride,
            const float* __restrict__ W, int wstride, int Ndim,
            const float* __restrict__ bias,
            __nv_bfloat16* __restrict__ Oh, __nv_bfloat16* __restrict__ Ol,
            float* __restrict__ Of) {
    extern __shared__ char smraw[];
    __nv_bfloat16* Bh = (__nv_bfloat16*)smraw;                       // 64*520*2
    __nv_bfloat16* Bl = Bh + BN * PKB;
    __nv_bfloat16* Ah = Bl + BN * PKB;                               // 128*72*2
    __nv_bfloat16* Al = Ah + BM * PKA;
    int* rowsrc = (int*)(Al + BM * PKA);

    const int e   = blockIdx.y;
    const int cnt = g_cnt[e];
    const int off = g_off[e];
    int n0, koff, ksl;
    if (SPLITK) { n0 = (blockIdx.x & 7) * BN; ksl = blockIdx.x >> 3; koff = ksl * KT; }
    else        { n0 = blockIdx.x * BN;       ksl = 0;               koff = 0; }

    const int tid  = threadIdx.x;
    const int lane = tid & 31;
    const int w    = tid >> 5;
    const int mwarp = (w >> 1) * 32;      // 4 warp-rows
    const int nwarp = (w & 1) * 32;       // 2 warp-cols
    constexpr int MT = 2, NT = 4;

    // ---- phase 1: convert W slice once into SMEM (hi/lo), full KT depth ----
    const float* Wexp = W + (size_t)e * Ndim * wstride + koff;
#pragma unroll 4
    for (int it = 0; it < BN * (KT / 4) / 256; it++) {
        int f = tid + it * 256;
        int row = f >> 7;                 // KT/4 = 128 quads per row
        int q   = f & 127;
        float4 v = *(const float4*)(Wexp + (size_t)(n0 + row) * wstride + 4 * q);
        uint32_t h01, h23, l01, l23;
        split4(v, h01, h23, l01, l23);
        *(uint2*)&Bh[row * PKB + 4 * q] = make_uint2(h01, h23);
        *(uint2*)&Bl[row * PKB + 4 * q] = make_uint2(l01, l23);
    }

    const uint32_t sAh = (uint32_t)__cvta_generic_to_shared(Ah);
    const uint32_t sAl = (uint32_t)__cvta_generic_to_shared(Al);
    const uint32_t sBh = (uint32_t)__cvta_generic_to_shared(Bh);
    const uint32_t sBl = (uint32_t)__cvta_generic_to_shared(Bl);

    // ---- phase 2: loop m-blocks ----
    for (int mb = 0; mb * BM < cnt; mb++) {
        __syncthreads();   // previous iter fully done (also orders W-convert on iter 0)
        if (tid < BM) {
            int gm = mb * BM + tid;
            rowsrc[tid] = (gm < cnt) ? (GATHER ? g_pair_token[off + gm] : (off + gm)) : -1;
        }
        __syncthreads();

        float acc[MT][NT][4];
#pragma unroll
        for (int i = 0; i < MT; i++)
#pragma unroll
            for (int j = 0; j < NT; j++)
#pragma unroll
                for (int c = 0; c < 4; c++) acc[i][j][c] = 0.f;

        // prime chunk 0 into regs
        uint4 vh[4], vl[4];
#pragma unroll
        for (int it = 0; it < 4; it++) {
            int f = tid + it * 256, row = f >> 3, q = f & 7;
            int src = rowsrc[row];
            if (src >= 0) {
                size_t base = (size_t)src * astride + koff + 8 * q;
                vh[it] = *(const uint4*)(Agh + base);
                vl[it] = *(const uint4*)(Agl + base);
            } else {
                vh[it] = make_uint4(0, 0, 0, 0); vl[it] = vh[it];
            }
        }

        for (int kc = 0; kc < KT; kc += BKC) {
#pragma unroll
            for (int it = 0; it < 4; it++) {
                int f = tid + it * 256, row = f >> 3, q = f & 7;
                *(uint4*)&Ah[row * PKA + 8 * q] = vh[it];
                *(uint4*)&Al[row * PKA + 8 * q] = vl[it];
            }
            __syncthreads();
            if (kc + BKC < KT) {
#pragma unroll
                for (int it = 0; it < 4; it++) {
                    int f = tid + it * 256, row = f >> 3, q = f & 7;
                    int src = rowsrc[row];
                    if (src >= 0) {
                        size_t base = (size_t)src * astride + koff + kc + BKC + 8 * q;
                        vh[it] = *(const uint4*)(Agh + base);
                        vl[it] = *(const uint4*)(Agl + base);
                    } else {
                        vh[it] = make_uint4(0, 0, 0, 0); vl[it] = vh[it];
                    }
                }
            }
#pragma unroll
            for (int ks = 0; ks < 4; ks++) {
                uint32_t fa_h[MT][4], fa_l[MT][4];
#pragma unroll
                for (int mt = 0; mt < MT; mt++) {
                    int row = mwarp + 16 * mt + (lane & 15);
                    int col = 16 * ks + ((lane >> 4) << 3);
                    uint32_t o = (uint32_t)(row * PKA + col) * 2;
                    ldsm_x4(sAh + o, fa_h[mt]);
                    ldsm_x4(sAl + o, fa_l[mt]);
                }
                uint32_t fb_h[2][4], fb_l[2][4];
#pragma unroll
                for (int np = 0; np < 2; np++) {
                    int row = nwarp + 16 * np + ((lane >> 4) << 3) + (lane & 7);
                    int col = kc + 16 * ks + (((lane >> 3) & 1) << 3);
                    uint32_t o = (uint32_t)(row * PKB + col) * 2;
                    ldsm_x4(sBh + o, fb_h[np]);
                    ldsm_x4(sBl + o, fb_l[np]);
                }
#pragma unroll
                for (int mt = 0; mt < MT; mt++)
#pragma unroll
                    for (int nt = 0; nt < NT; nt++) {
                        int np = nt >> 1, half = (nt & 1) << 1;
                        uint32_t bh0 = fb_h[np][half], bh1 = fb_h[np][half + 1];
                        uint32_t bl0 = fb_l[np][half], bl1 = fb_l[np][half + 1];
                        mma_bf16(acc[mt][nt], fa_h[mt], bh0, bh1);
                        mma_bf16(acc[mt][nt], fa_h[mt], bl0, bl1);
                        mma_bf16(acc[mt][nt], fa_l[mt], bh0, bh1);
                    }
            }
            __syncthreads();
        }

        // ---- epilogue for this m-block ----
        const int g = lane >> 2, tig = lane & 3;
#pragma unroll
        for (int mt = 0; mt < MT; mt++) {
            int mloc0 = mb * BM + mwarp + 16 * mt + g;
#pragma unroll
            for (int nt = 0; nt < NT; nt++) {
                int nglob = n0 + nwarp + 8 * nt + 2 * tig;
                float b0 = 0.f, b1 = 0.f;
                if (EPI == 0 || ksl == 0) {
                    b0 = bias[e * Ndim + nglob];
                    b1 = bias[e * Ndim + nglob + 1];
                }
                float v0 = acc[mt][nt][0] + b0;
                float v1 = acc[mt][nt][1] + b1;
                float v2 = acc[mt][nt][2] + b0;
                float v3 = acc[mt][nt][3] + b1;
                if (EPI == 0) {
                    v0 = gelu_erf(v0); v1 = gelu_erf(v1);
                    v2 = gelu_erf(v2); v3 = gelu_erf(v3);
                    uint32_t h, l;
                    if (mloc0 < cnt) {
                        size_t o = (size_t)(off + mloc0) * Ndim + nglob;
                        split2(v0, v1, h, l);
                        *(uint32_t*)&Oh[o] = h; *(uint32_t*)&Ol[o] = l;
                    }
                    if (mloc0 + 8 < cnt) {
                        size_t o = (size_t)(off + mloc0 + 8) * Ndim + nglob;
                        split2(v2, v3, h, l);
                        *(uint32_t*)&Oh[o] = h; *(uint32_t*)&Ol[o] = l;
                    }
                } else {
                    float* dst = Of + (size_t)ksl * NPAIR * DMODEL;
                    if (mloc0 < cnt)
                        *(float2*)&dst[(size_t)(off + mloc0) * Ndim + nglob] =
                            make_float2(v0, v1);
                    if (mloc0 + 8 < cnt)
                        *(float2*)&dst[(size_t)(off + mloc0 + 8) * Ndim + nglob] =
                            make_float2(v2, v3);
                }
            }
        }
    }
}

// ---------------- combine partials + LayerNorm ----------------
__global__ void combine_ln(const float* __restrict__ lnw,
                           const float* __restrict__ lnb,
                           float* __restrict__ out) {
    int n = blockIdx.x;
    int t = threadIdx.x;                     // 128 threads
    float s0 = g_score[n * 2 + 0], s1 = g_score[n * 2 + 1];
    const float* r0 = g_y2p + (size_t)g_pos[n * 2 + 0] * DMODEL;
    const float* r1 = g_y2p + (size_t)g_pos[n * 2 + 1] * DMODEL;
    const size_t S = (size_t)NPAIR * DMODEL;
    float v[4];
    float sum = 0.f, sumsq = 0.f;
#pragma unroll
    for (int j = 0; j < 4; j++) {
        int d = t + j * 128;
        float a = r0[d] + r0[S + d] + r0[2 * S + d] + r0[3 * S + d];
        float b = r1[d] + r1[S + d] + r1[2 * S + d] + r1[3 * S + d];
        float x = s0 * a + s1 * b;
        v[j] = x; sum += x; sumsq += x * x;
    }
    __shared__ float red[64];
#pragma unroll
    for (int o = 16; o; o >>= 1) {
        sum   += __shfl_xor_sync(~0u, sum, o);
        sumsq += __shfl_xor_sync(~0u, sumsq, o);
    }
    int w = t >> 5, l = t & 31;
    if (l == 0) { red[w] = sum; red[32 + w] = sumsq; }
    __syncthreads();
    if (t < 32) {
        float a = (l < 4) ? red[l] : 0.f;
        float b = (l < 4) ? red[32 + l] : 0.f;
#pragma unroll
        for (int o = 2; o; o >>= 1) {
            a += __shfl_xor_sync(~0u, a, o);
            b += __shfl_xor_sync(~0u, b, o);
        }
        if (l == 0) { red[0] = a; red[1] = b; }
    }
    __syncthreads();
    float mean = red[0] * (1.0f / DMODEL);
    float var  = red[1] * (1.0f / DMODEL) - mean * mean;
    float rstd = rsqrtf(var + 1e-5f);
#pragma unroll
    for (int j = 0; j < 4; j++) {
        int d = t + j * 128;
        out[(size_t)n * DMODEL + d] = (v[j] - mean) * rstd * lnw[d] + lnb[d];
    }
}

// ---------------- launch ----------------
extern "C" void kernel_launch(void* const* d_in, const int* in_sizes, int n_in,
                              void* d_out, int out_size) {
    const float* inp    = (const float*)d_in[0];
    const float* gate_w = (const float*)d_in[1];
    const float* gate_b = (const float*)d_in[2];
    const float* w1     = (const float*)d_in[3];
    const float* b1     = (const float*)d_in[4];
    const float* w2     = (const float*)d_in[5];
    const float* b2     = (const float*)d_in[6];
    const float* ln_w   = (const float*)d_in[7];
    const float* ln_b   = (const float*)d_in[8];
    float* out = (float*)d_out;

    __nv_bfloat16 *inph, *inpl, *hh, *hl; float* y2p;
    cudaGetSymbolAddress((void**)&inph, g_inph);
    cudaGetSymbolAddress((void**)&inpl, g_inpl);
    cudaGetSymbolAddress((void**)&hh,   g_hh);
    cudaGetSymbolAddress((void**)&hl,   g_hl);
    cudaGetSymbolAddress((void**)&y2p,  g_y2p);

    const int SMEM_SZ = (BN * PKB * 2 + BM * PKA * 2) * 2 + BM * 4;  // ~170.5KB
    cudaFuncSetAttribute(moe_fc<0, true,  false>,
                         cudaFuncAttributeMaxDynamicSharedMemorySize, SMEM_SZ);
    cudaFuncSetAttribute(moe_fc<1, false, true>,
                         cudaFuncAttributeMaxDynamicSharedMemorySize, SMEM_SZ);

    cvt_inp<<<NTOK * DMODEL / 4 / 256, 256>>>(inp);
    gate_kernel<<<NTOK / 8, 256>>>(inp, gate_w, gate_b);
    scan_scatter<<<1, 1024>>>();

    // FC1: weight-stationary, 32 n-slices x 8 experts
    {
        dim3 grid(HID / BN, NEXP);
        moe_fc<0, true, false><<<grid, 256, SMEM_SZ>>>(
            inph, inpl, DMODEL, w1, DMODEL, HID, b1, hh, hl, nullptr);
    }
    // FC2: split-K (4 x 512), 8 n-slices x 4 k-slices x 8 experts
    {
        dim3 grid((DMODEL / BN) * KSPLIT, NEXP);
        moe_fc<1, false, true><<<grid, 256, SMEM_SZ>>>(
            hh, hl, HID, w2, HID, DMODEL, b2, nullptr, nullptr, y2p);
    }
    combine_ln<<<NTOK, 128>>>(ln_w, ln_b, out);
}

// round 7
// speedup vs baseline: 1.1118x; 1.1118x over previous
#include <cuda_runtime.h>
#include <cuda_bf16.h>
#include <math.h>
#include <stdint.h>

// Problem constants
#define NTOK 1024
#define DMODEL 512
#define HID 2048
#define NEXP 8
#define NPAIR 2048
#define NSPLIT2 2        // FC2 split-K

// ---------------- scratch (device globals; no allocation) ----------------
__device__ __nv_bfloat16 g_inph[NTOK * DMODEL];          // 1MB each
__device__ __nv_bfloat16 g_inpl[NTOK * DMODEL];
__device__ __nv_bfloat16 g_w1h[NEXP * HID * DMODEL];     // 16.8MB each
__device__ __nv_bfloat16 g_w1l[NEXP * HID * DMODEL];
__device__ __nv_bfloat16 g_w2h[NEXP * DMODEL * HID];
__device__ __nv_bfloat16 g_w2l[NEXP * DMODEL * HID];
__device__ __nv_bfloat16 g_hh[NPAIR * HID];              // 8MB each
__device__ __nv_bfloat16 g_hl[NPAIR * HID];
__device__ float g_y2p[NSPLIT2 * NPAIR * DMODEL];        // 8.4MB
__device__ int   g_cnt[NEXP];
__device__ int   g_off[NEXP];
__device__ int   g_tokexp[NPAIR];
__device__ float g_score[NPAIR];
__device__ int   g_pos[NPAIR];
__device__ int   g_pair_token[NPAIR];

// ---------------- numeric helpers ----------------
__device__ __forceinline__ uint32_t b2u(__nv_bfloat162 v) {
    return *reinterpret_cast<uint32_t*>(&v);
}
// truncation split: hi = truncate-to-bf16, lo = rn(x - hi)
__device__ __forceinline__ void split4(float4 v, uint32_t& h01, uint32_t& h23,
                                       uint32_t& l01, uint32_t& l23) {
    uint32_t bx = __float_as_uint(v.x), by = __float_as_uint(v.y);
    uint32_t bz = __float_as_uint(v.z), bw = __float_as_uint(v.w);
    h01 = __byte_perm(bx, by, 0x7632);
    h23 = __byte_perm(bz, bw, 0x7632);
    float r0 = v.x - __uint_as_float(bx & 0xffff0000u);
    float r1 = v.y - __uint_as_float(by & 0xffff0000u);
    float r2 = v.z - __uint_as_float(bz & 0xffff0000u);
    float r3 = v.w - __uint_as_float(bw & 0xffff0000u);
    l01 = b2u(__floats2bfloat162_rn(r0, r1));
    l23 = b2u(__floats2bfloat162_rn(r2, r3));
}
__device__ __forceinline__ void split2(float x, float y, uint32_t& h, uint32_t& l) {
    uint32_t bx = __float_as_uint(x), by = __float_as_uint(y);
    h = __byte_perm(bx, by, 0x7632);
    float r0 = x - __uint_as_float(bx & 0xffff0000u);
    float r1 = y - __uint_as_float(by & 0xffff0000u);
    l = b2u(__floats2bfloat162_rn(r0, r1));
}
// erf-GELU via A&S 7.1.26 (|err_erf| < 1.5e-7)
__device__ __forceinline__ float gelu_erf(float x) {
    float z = fabsf(x) * 0.70710678118654752f;
    float t = __frcp_rn(fmaf(0.3275911f, z, 1.0f));
    float p = fmaf(fmaf(fmaf(fmaf(1.061405429f, t, -1.453152027f), t,
                             1.421413741f), t, -0.284496736f), t, 0.254829592f) * t;
    float er = 1.0f - p * __expf(-z * z);
    return x * 0.5f * (1.0f + copysignf(er, x));
}
__device__ __forceinline__ void ldsm_x4(uint32_t addr, uint32_t* r) {
    asm volatile("ldmatrix.sync.aligned.m8n8.x4.shared.b16 {%0,%1,%2,%3}, [%4];"
                 : "=r"(r[0]), "=r"(r[1]), "=r"(r[2]), "=r"(r[3]) : "r"(addr));
}
__device__ __forceinline__ void mma_bf16(float* d, const uint32_t* a,
                                         uint32_t b0, uint32_t b1) {
    asm volatile("mma.sync.aligned.m16n8k16.row.col.f32.bf16.bf16.f32 "
                 "{%0,%1,%2,%3},{%4,%5,%6,%7},{%8,%9},{%0,%1,%2,%3};"
                 : "+f"(d[0]), "+f"(d[1]), "+f"(d[2]), "+f"(d[3])
                 : "r"(a[0]), "r"(a[1]), "r"(a[2]), "r"(a[3]), "r"(b0), "r"(b1));
}

// ---------------- conversion kernel (fp32 -> bf16 hi/lo), one pass ----------------
__global__ void cvt_split(const float* __restrict__ x,
                          __nv_bfloat16* __restrict__ dh,
                          __nv_bfloat16* __restrict__ dl, int nquads) {
    int i = blockIdx.x * blockDim.x + threadIdx.x;
    if (i >= nquads) return;
    float4 v = reinterpret_cast<const float4*>(x)[i];
    uint32_t h01, h23, l01, l23;
    split4(v, h01, h23, l01, l23);
    reinterpret_cast<uint2*>(dh)[i] = make_uint2(h01, h23);
    reinterpret_cast<uint2*>(dl)[i] = make_uint2(l01, l23);
}

// ---------------- gate (one warp per token, no atomics) ----------------
__global__ void gate_kernel(const float* __restrict__ inp,
                            const float* __restrict__ gw,
                            const float* __restrict__ gb) {
    int tok  = (blockIdx.x * blockDim.x + threadIdx.x) >> 5;
    int lane = threadIdx.x & 31;
    if (tok >= NTOK) return;
    const float* x = inp + (size_t)tok * DMODEL;
    float acc[NEXP];
#pragma unroll
    for (int e = 0; e < NEXP; e++) acc[e] = 0.f;
    for (int d = lane; d < DMODEL; d += 32) {
        float xv = x[d];
#pragma unroll
        for (int e = 0; e < NEXP; e++) acc[e] += xv * gw[e * DMODEL + d];
    }
#pragma unroll
    for (int e = 0; e < NEXP; e++)
#pragma unroll
        for (int o = 16; o; o >>= 1) acc[e] += __shfl_xor_sync(~0u, acc[e], o);
    if (lane == 0) {
        float best = -1e30f, best2 = -1e30f; int bi = 0, bi2 = 0;
#pragma unroll
        for (int e = 0; e < NEXP; e++) {
            float v = acc[e] + gb[e];
            if (v > best)       { best2 = best; bi2 = bi; best = v; bi = e; }
            else if (v > best2) { best2 = v; bi2 = e; }
        }
        float ed = expf(best2 - best);
        g_tokexp[tok * 2 + 0] = bi;
        g_tokexp[tok * 2 + 1] = bi2;
        g_score[tok * 2 + 0] = 1.f / (1.f + ed);
        g_score[tok * 2 + 1] = ed / (1.f + ed);
    }
}

// ---------------- scan + scatter (single block, shared atomics) ----------------
__global__ void scan_scatter() {
    __shared__ int hist[NEXP], cur[NEXP];
    int t = threadIdx.x;
    if (t < NEXP) hist[t] = 0;
    __syncthreads();
    int e0 = g_tokexp[t], e1 = g_tokexp[t + 1024];
    atomicAdd(&hist[e0], 1);
    atomicAdd(&hist[e1], 1);
    __syncthreads();
    if (t == 0) {
        int s = 0;
        for (int e = 0; e < NEXP; e++) {
            g_off[e] = s; cur[e] = s; g_cnt[e] = hist[e]; s += hist[e];
        }
    }
    __syncthreads();
    int p0 = atomicAdd(&cur[e0], 1);
    g_pos[t] = p0; g_pair_token[p0] = t >> 1;
    int p1 = atomicAdd(&cur[e1], 1);
    g_pos[t + 1024] = p1; g_pair_token[p1] = (t + 1024) >> 1;
}

// ---------------- grouped GEMM, pre-converted bf16 hi/lo, 3-term MMA ----------------
// C[p][n] = sum_k A[row][k] * W[e][n][k] (+bias)
// EPI 0: bias+GELU -> bf16 hi/lo.  EPI 1: fp32 partial (+bias if ksl==0).
template<int BM, int BN, int EPI, bool GATHER, int NSPLIT>
__global__ __launch_bounds__(256, 1)
void moe_gemm(const __nv_bfloat16* __restrict__ Agh,
              const __nv_bfloat16* __restrict__ Agl,
              int astride,
              const __nv_bfloat16* __restrict__ Wh,
              const __nv_bfloat16* __restrict__ Wl,
              int Kfull, int Ndim,
              const float* __restrict__ bias,
              __nv_bfloat16* __restrict__ Oh, __nv_bfloat16* __restrict__ Ol,
              float* __restrict__ Of) {
    constexpr int BK = 32;
    constexpr int PK = 40;                  // pitch (elems), 80B rows
    constexpr int WC = 4, WR = 2;
    constexpr int WM = BM / WR, WN = BN / WC;
    constexpr int MT = WM / 16, NT = WN / 8;
    constexpr int A_IT = BM * 4 / 256;      // 16B granules per thread
    constexpr int B_IT = BN * 4 / 256;
    constexpr int NBLK = 1;                 // placeholder

    const int e   = blockIdx.z;
    const int cnt = g_cnt[e];
    const int m0  = blockIdx.y * BM;
    if (m0 >= cnt) return;
    const int nb    = blockIdx.x % (Ndim / BN);
    const int ksl   = blockIdx.x / (Ndim / BN);
    const int n0    = nb * BN;
    const int klen  = Kfull / NSPLIT;
    const int kbase = ksl * klen;
    const int off   = g_off[e];

    __shared__ __nv_bfloat16 Ah[BM * PK], Al[BM * PK];
    __shared__ __nv_bfloat16 Bh[BN * PK], Bl[BN * PK];
    __shared__ int rowsrc[BM];

    const int tid  = threadIdx.x;
    const int lane = tid & 31;
    const int w    = tid >> 5;
    const int mwarp = (w >> 2) * WM;
    const int nwarp = (w & 3) * WN;

    if (tid < BM) {
        int gm = m0 + tid; int r = -1;
        if (gm < cnt) r = GATHER ? g_pair_token[off + gm] : (off + gm);
        rowsrc[tid] = r;
    }
    __syncthreads();

    // per-thread global pointers
    const __nv_bfloat16* pAh[A_IT];
    const __nv_bfloat16* pAl[A_IT];
    const __nv_bfloat16* pBh[B_IT];
    const __nv_bfloat16* pBl[B_IT];
#pragma unroll
    for (int i = 0; i < A_IT; i++) {
        int f = tid + i * 256, row = f >> 2, g = f & 3;
        int src = rowsrc[row];
        size_t o = (size_t)(src < 0 ? 0 : src) * astride + kbase + g * 8;
        pAh[i] = (src >= 0) ? (Agh + o) : nullptr;
        pAl[i] = Agl + o;
    }
    const size_t wexp = (size_t)e * Ndim * Kfull;
#pragma unroll
    for (int i = 0; i < B_IT; i++) {
        int f = tid + i * 256, row = f >> 2, g = f & 3;
        size_t o = wexp + (size_t)(n0 + row) * Kfull + kbase + g * 8;
        pBh[i] = Wh + o;
        pBl[i] = Wl + o;
    }

    float acc[MT][NT][4];
#pragma unroll
    for (int i = 0; i < MT; i++)
#pragma unroll
        for (int j = 0; j < NT; j++)
#pragma unroll
            for (int c = 0; c < 4; c++) acc[i][j][c] = 0.f;

    uint4 vah[A_IT], val[A_IT], vbh[B_IT], vbl[B_IT];
#pragma unroll
    for (int i = 0; i < A_IT; i++) {
        if (pAh[i]) { vah[i] = *(const uint4*)pAh[i]; val[i] = *(const uint4*)pAl[i]; }
        else        { vah[i] = make_uint4(0,0,0,0); val[i] = vah[i]; }
    }
#pragma unroll
    for (int i = 0; i < B_IT; i++) {
        vbh[i] = *(const uint4*)pBh[i];
        vbl[i] = *(const uint4*)pBl[i];
    }

    const uint32_t sAh = (uint32_t)__cvta_generic_to_shared(Ah);
    const uint32_t sAl = (uint32_t)__cvta_generic_to_shared(Al);
    const uint32_t sBh = (uint32_t)__cvta_generic_to_shared(Bh);
    const uint32_t sBl = (uint32_t)__cvta_generic_to_shared(Bl);

    for (int kc = 0; kc < klen; kc += BK) {
#pragma unroll
        for (int i = 0; i < A_IT; i++) {
            int f = tid + i * 256, row = f >> 2, g = f & 3;
            *(uint4*)&Ah[row * PK + g * 8] = vah[i];
            *(uint4*)&Al[row * PK + g * 8] = val[i];
        }
#pragma unroll
        for (int i = 0; i < B_IT; i++) {
            int f = tid + i * 256, row = f >> 2, g = f & 3;
            *(uint4*)&Bh[row * PK + g * 8] = vbh[i];
            *(uint4*)&Bl[row * PK + g * 8] = vbl[i];
        }
        __syncthreads();

        if (kc + BK < klen) {
#pragma unroll
            for (int i = 0; i < A_IT; i++) {
                if (pAh[i]) { vah[i] = *(const uint4*)(pAh[i] + kc + BK);
                              val[i] = *(const uint4*)(pAl[i] + kc + BK); }
            }
#pragma unroll
            for (int i = 0; i < B_IT; i++) {
                vbh[i] = *(const uint4*)(pBh[i] + kc + BK);
                vbl[i] = *(const uint4*)(pBl[i] + kc + BK);
            }
        }

#pragma unroll
        for (int ks = 0; ks < 2; ks++) {
            uint32_t fa_h[MT][4], fa_l[MT][4];
#pragma unroll
            for (int mt = 0; mt < MT; mt++) {
                int row = mwarp + 16 * mt + (lane & 15);
                int col = 16 * ks + ((lane >> 4) << 3);
                uint32_t o = (uint32_t)(row * PK + col) * 2;
                ldsm_x4(sAh + o, fa_h[mt]);
                ldsm_x4(sAl + o, fa_l[mt]);
            }
            uint32_t fb_h[NT / 2][4], fb_l[NT / 2][4];
#pragma unroll
            for (int np = 0; np < NT / 2; np++) {
                int row = nwarp + 16 * np + ((lane >> 4) << 3) + (lane & 7);
                int col = 16 * ks + (((lane >> 3) & 1) << 3);
                uint32_t o = (uint32_t)(row * PK + col) * 2;
                ldsm_x4(sBh + o, fb_h[np]);
                ldsm_x4(sBl + o, fb_l[np]);
            }
#pragma unroll
            for (int mt = 0; mt < MT; mt++)
#pragma unroll
                for (int nt = 0; nt < NT; nt++) {
                    int np = nt >> 1, hf = (nt & 1) << 1;
                    uint32_t bh0 = fb_h[np][hf], bh1 = fb_h[np][hf + 1];
                    uint32_t bl0 = fb_l[np][hf], bl1 = fb_l[np][hf + 1];
                    mma_bf16(acc[mt][nt], fa_h[mt], bh0, bh1);
                    mma_bf16(acc[mt][nt], fa_h[mt], bl0, bl1);
                    mma_bf16(acc[mt][nt], fa_l[mt], bh0, bh1);
                }
        }
        __syncthreads();
    }

    // ---- epilogue ----
    const int g = lane >> 2, tig = lane & 3;
#pragma unroll
    for (int mt = 0; mt < MT; mt++) {
#pragma unroll
        for (int nt = 0; nt < NT; nt++) {
            int col = n0 + nwarp + 8 * nt + 2 * tig;
            float b0 = 0.f, b1 = 0.f;
            if (EPI == 0 || ksl == 0) {
                b0 = bias[e * Ndim + col];
                b1 = bias[e * Ndim + col + 1];
            }
            int r0 = m0 + mwarp + 16 * mt + g;
            int r1 = r0 + 8;
            float v0 = acc[mt][nt][0] + b0;
            float v1 = acc[mt][nt][1] + b1;
            float v2 = acc[mt][nt][2] + b0;
            float v3 = acc[mt][nt][3] + b1;
            if (EPI == 0) {
                v0 = gelu_erf(v0); v1 = gelu_erf(v1);
                v2 = gelu_erf(v2); v3 = gelu_erf(v3);
                uint32_t h, l;
                if (r0 < cnt) {
                    size_t o = (size_t)(off + r0) * Ndim + col;
                    split2(v0, v1, h, l);
                    *(uint32_t*)&Oh[o] = h; *(uint32_t*)&Ol[o] = l;
                }
                if (r1 < cnt) {
                    size_t o = (size_t)(off + r1) * Ndim + col;
                    split2(v2, v3, h, l);
                    *(uint32_t*)&Oh[o] = h; *(uint32_t*)&Ol[o] = l;
                }
            } else {
                float* dst = Of + (size_t)ksl * NPAIR * DMODEL;
                if (r0 < cnt)
                    *(float2*)&dst[(size_t)(off + r0) * Ndim + col] = make_float2(v0, v1);
                if (r1 < cnt)
                    *(float2*)&dst[(size_t)(off + r1) * Ndim + col] = make_float2(v2, v3);
            }
        }
    }
}

// ---------------- combine partials + LayerNorm ----------------
__global__ void combine_ln(const float* __restrict__ lnw,
                           const float* __restrict__ lnb,
                           float* __restrict__ out) {
    int n = blockIdx.x;
    int t = threadIdx.x;                     // 128 threads
    float s0 = g_score[n * 2 + 0], s1 = g_score[n * 2 + 1];
    const float* r0 = g_y2p + (size_t)g_pos[n * 2 + 0] * DMODEL;
    const float* r1 = g_y2p + (size_t)g_pos[n * 2 + 1] * DMODEL;
    const size_t S = (size_t)NPAIR * DMODEL;
    float v[4];
    float sum = 0.f, sumsq = 0.f;
#pragma unroll
    for (int j = 0; j < 4; j++) {
        int d = t + j * 128;
        float a = r0[d] + r0[S + d];
        float b = r1[d] + r1[S + d];
        float x = s0 * a + s1 * b;
        v[j] = x; sum += x; sumsq += x * x;
    }
    __shared__ float red[64];
#pragma unroll
    for (int o = 16; o; o >>= 1) {
        sum   += __shfl_xor_sync(~0u, sum, o);
        sumsq += __shfl_xor_sync(~0u, sumsq, o);
    }
    int w = t >> 5, l = t & 31;
    if (l == 0) { red[w] = sum; red[32 + w] = sumsq; }
    __syncthreads();
    if (t < 32) {
        float a = (l < 4) ? red[l] : 0.f;
        float b = (l < 4) ? red[32 + l] : 0.f;
#pragma unroll
        for (int o = 2; o; o >>= 1) {
            a += __shfl_xor_sync(~0u, a, o);
            b += __shfl_xor_sync(~0u, b, o);
        }
        if (l == 0) { red[0] = a; red[1] = b; }
    }
    __syncthreads();
    float mean = red[0] * (1.0f / DMODEL);
    float var  = red[1] * (1.0f / DMODEL) - mean * mean;
    float rstd = rsqrtf(var + 1e-5f);
#pragma unroll
    for (int j = 0; j < 4; j++) {
        int d = t + j * 128;
        out[(size_t)n * DMODEL + d] = (v[j] - mean) * rstd * lnw[d] + lnb[d];
    }
}

// ---------------- launch ----------------
extern "C" void kernel_launch(void* const* d_in, const int* in_sizes, int n_in,
                              void* d_out, int out_size) {
    const float* inp    = (const float*)d_in[0];
    const float* gate_w = (const float*)d_in[1];
    const float* gate_b = (const float*)d_in[2];
    const float* w1     = (const float*)d_in[3];
    const float* b1     = (const float*)d_in[4];
    const float* w2     = (const float*)d_in[5];
    const float* b2     = (const float*)d_in[6];
    const float* ln_w   = (const float*)d_in[7];
    const float* ln_b   = (const float*)d_in[8];
    float* out = (float*)d_out;

    __nv_bfloat16 *inph, *inpl, *w1h, *w1l, *w2h, *w2l, *hh, *hl;
    float* y2p;
    cudaGetSymbolAddress((void**)&inph, g_inph);
    cudaGetSymbolAddress((void**)&inpl, g_inpl);
    cudaGetSymbolAddress((void**)&w1h,  g_w1h);
    cudaGetSymbolAddress((void**)&w1l,  g_w1l);
    cudaGetSymbolAddress((void**)&w2h,  g_w2h);
    cudaGetSymbolAddress((void**)&w2l,  g_w2l);
    cudaGetSymbolAddress((void**)&hh,   g_hh);
    cudaGetSymbolAddress((void**)&hl,   g_hl);
    cudaGetSymbolAddress((void**)&y2p,  g_y2p);

    const int WQ = NEXP * HID * DMODEL / 4;   // weight quads (same for w1/w2)
    cvt_split<<<(NTOK * DMODEL / 4 + 255) / 256, 256>>>(inp, inph, inpl,
                                                        NTOK * DMODEL / 4);
    cvt_split<<<(WQ + 255) / 256, 256>>>(w1, w1h, w1l, WQ);
    cvt_split<<<(WQ + 255) / 256, 256>>>(w2, w2h, w2l, WQ);
    gate_kernel<<<NTOK / 8, 256>>>(inp, gate_w, gate_b);
    scan_scatter<<<1, 1024>>>();

    // FC1: inp(bf16 hi/lo) x w1^T -> hidden (bf16 hi/lo), GELU
    {
        dim3 grid(HID / 128, NPAIR / 128, NEXP);
        moe_gemm<128, 128, 0, true, 1><<<grid, 256>>>(
            inph, inpl, DMODEL, w1h, w1l, DMODEL, HID, b1, hh, hl, nullptr);
    }
    // FC2: hidden x w2^T -> y2 partials (split-K 2)
    {
        dim3 grid((DMODEL / 128) * NSPLIT2, NPAIR / 64, NEXP);
        moe_gemm<64, 128, 1, false, NSPLIT2><<<grid, 256>>>(
            hh, hl, HID, w2h, w2l, HID, DMODEL, b2, nullptr, nullptr, y2p);
    }
    combine_ln<<<NTOK, 128>>>(ln_w, ln_b, out);
}